// round 2
// baseline (speedup 1.0000x reference)
#include <cuda_runtime.h>
#include <math.h>

#define BATCH 128
#define SEQ   4096
#define SD    5
#define HID   32
#define DIN   9
#define NTOK  (BATCH*SEQ)
#define TPB   256

__device__ float g_temp[NTOK];

// ---------- f32x2 packed helpers (sm_103a) ----------
typedef unsigned long long ull;

__device__ __forceinline__ ull pk(float lo, float hi) {
    ull r; asm("mov.b64 %0, {%1, %2};" : "=l"(r) : "f"(lo), "f"(hi)); return r;
}
__device__ __forceinline__ void upk(float& lo, float& hi, ull v) {
    asm("mov.b64 {%0, %1}, %2;" : "=f"(lo), "=f"(hi) : "l"(v));
}
__device__ __forceinline__ void ffma2(ull& d, ull a, ull b) {
    asm("fma.rn.f32x2 %0, %1, %2, %0;" : "+l"(d) : "l"(a), "l"(b));
}

// MUFU tanh (hidden layers only; error contracted by downstream weights)
__device__ __forceinline__ float tanh_apx(float x) {
    float y; asm("tanh.approx.f32 %0, %1;" : "=f"(y) : "f"(x)); return y;
}
// accurate tanh for the output-facing c_n path
__device__ __forceinline__ float tanh_acc(float x) {
    float ax = fabsf(x);
    float e  = __expf(-2.0f * ax);
    float r  = __fdividef(1.0f - e, 1.0f + e);
    return copysignf(r, x);
}

// -------------------------------------------------------------------------
// Kernel 1: per-batch-row inclusive cumsum of delta_x[..., 2] plus init temp
// -------------------------------------------------------------------------
__global__ __launch_bounds__(1024) void cumsum_kernel(const float* __restrict__ dx) {
    __shared__ float ssum[1024];
    const int b   = blockIdx.x;
    const int tid = threadIdx.x;
    const float* row = dx + (size_t)b * SEQ * 6;

    const int s0 = tid * 4;
    float v0 = row[(s0 + 0) * 6 + 2];
    float v1 = row[(s0 + 1) * 6 + 2];
    float v2 = row[(s0 + 2) * 6 + 2];
    float v3 = row[(s0 + 3) * 6 + 2];
    float tot = (v0 + v1) + (v2 + v3);

    ssum[tid] = tot;
    __syncthreads();

    float acc = tot;
    #pragma unroll
    for (int off = 1; off < 1024; off <<= 1) {
        float add = (tid >= off) ? ssum[tid - off] : 0.0f;
        __syncthreads();
        acc += add;
        ssum[tid] = acc;
        __syncthreads();
    }

    float init = row[5];
    float base = init + (acc - tot);
    float r0 = base + v0;
    float r1 = r0 + v1;
    float r2 = r1 + v2;
    float r3 = r2 + v3;

    float* out = g_temp + (size_t)b * SEQ + s0;
    out[0] = r0; out[1] = r1; out[2] = r2; out[3] = r3;
}

// -------------------------------------------------------------------------
// Kernel 2: per-token MLP with f32x2 packed gate pairs + LDS.128 weights
// -------------------------------------------------------------------------
__global__ __launch_bounds__(TPB) void msc_main(
    const float* __restrict__ h_prev,  const float* __restrict__ delta_x,
    const float* __restrict__ Wa0,     const float* __restrict__ ba0,
    const float* __restrict__ Wb0,     const float* __restrict__ bb0,
    const float* __restrict__ Wa1,     const float* __restrict__ ba1,
    const float* __restrict__ Wb1,     const float* __restrict__ bb1,
    const float* __restrict__ W_alpha, const float* __restrict__ b_alpha,
    const float* __restrict__ W_beta,  const float* __restrict__ b_beta,
    const float* __restrict__ W_gamma, const float* __restrict__ b_gamma,
    const float* __restrict__ W_c,     const float* __restrict__ b_c,
    const float* __restrict__ W_out,
    float* __restrict__ out)
{
    // weight pair interleave: sW[i][jj] = (Wa[i][2jj], Wb[i][2jj], Wa[i][2jj+1], Wb[i][2jj+1])
    __shared__ float4 sW0[DIN * HID / 2];   // 144 * 16B
    __shared__ float4 sW1[HID * HID / 2];   // 512 * 16B
    __shared__ float2 sB0[HID], sB1[HID];   // (ba[j], bb[j])
    __shared__ float2 sH0[HID];             // (W_alpha[j], W_beta[j])
    __shared__ float2 sH1[HID];             // (W_gamma[j], W_c[j][0])
    __shared__ float2 sH2[HID];             // (W_c[j][1], W_c[j][2])
    __shared__ float2 sH3[HID];             // (W_c[j][3], W_c[j][4])
    __shared__ float  sWout[SD], sbc[SD];
    __shared__ float  sbal, sbbe, sbga;

    const int tid = threadIdx.x;

    for (int idx = tid; idx < DIN * HID / 2; idx += TPB) {
        int i = idx >> 4, jj = idx & 15, j0 = jj * 2;
        sW0[idx] = make_float4(Wa0[i * HID + j0],     Wb0[i * HID + j0],
                               Wa0[i * HID + j0 + 1], Wb0[i * HID + j0 + 1]);
    }
    for (int idx = tid; idx < HID * HID / 2; idx += TPB) {
        int i = idx >> 4, jj = idx & 15, j0 = jj * 2;
        sW1[idx] = make_float4(Wa1[i * HID + j0],     Wb1[i * HID + j0],
                               Wa1[i * HID + j0 + 1], Wb1[i * HID + j0 + 1]);
    }
    if (tid < HID) {
        sB0[tid] = make_float2(ba0[tid], bb0[tid]);
        sB1[tid] = make_float2(ba1[tid], bb1[tid]);
        sH0[tid] = make_float2(W_alpha[tid], W_beta[tid]);
        sH1[tid] = make_float2(W_gamma[tid], W_c[tid * SD + 0]);
        sH2[tid] = make_float2(W_c[tid * SD + 1], W_c[tid * SD + 2]);
        sH3[tid] = make_float2(W_c[tid * SD + 3], W_c[tid * SD + 4]);
    }
    if (tid < SD) { sWout[tid] = W_out[tid]; sbc[tid] = b_c[tid]; }
    if (tid == 0) { sbal = b_alpha[0]; sbbe = b_beta[0]; sbga = b_gamma[0]; }
    __syncthreads();

    const int t = blockIdx.x * TPB + tid;

    const float* hp = h_prev  + (size_t)t * SD;
    const float* dx = delta_x + (size_t)t * 6;

    float h[SD];
    #pragma unroll
    for (int k = 0; k < SD; k++) h[k] = hp[k];

    const float df0 = dx[0], df1 = dx[1], df2 = dx[2];
    const float temp = g_temp[t];

    float nrm = sqrtf(fmaf(df0, df0, fmaf(df1, df1, df2 * df2)));
    nrm = fmaxf(nrm, 1e-7f);
    const float inv = __fdividef(1.0f, nrm);

    // dup-packed input vector
    ull l2[DIN];
    l2[0] = pk(h[0], h[0]); l2[1] = pk(h[1], h[1]); l2[2] = pk(h[2], h[2]);
    l2[3] = pk(h[3], h[3]); l2[4] = pk(h[4], h[4]);
    l2[5] = pk(temp, temp);
    { float d = df0 * inv; l2[6] = pk(d, d); }
    { float d = df1 * inv; l2[7] = pk(d, d); }
    { float d = df2 * inv; l2[8] = pk(d, d); }

    // ---------------- layer 0: 9 -> 32 gated ----------------
    ull u2[HID];  // dup-packed activations for layer 1
    #pragma unroll
    for (int jj = 0; jj < HID / 2; jj++) {
        float2 b0 = sB0[2 * jj], b1 = sB0[2 * jj + 1];
        ull a0 = pk(b0.x, b0.y);
        ull a1 = pk(b1.x, b1.y);
        #pragma unroll
        for (int i = 0; i < DIN; i++) {
            float4 w = sW0[i * (HID / 2) + jj];
            ffma2(a0, l2[i], pk(w.x, w.y));
            ffma2(a1, l2[i], pk(w.z, w.w));
        }
        float x, y;
        upk(x, y, a0); float ua = tanh_apx(x) * tanh_apx(y);
        upk(x, y, a1); float ub = tanh_apx(x) * tanh_apx(y);
        u2[2 * jj]     = pk(ua, ua);
        u2[2 * jj + 1] = pk(ub, ub);
    }

    // ---------------- layer 1 (32->32 gated) fused with heads ----------------
    ull A0 = pk(sbal, sbbe);          // (alpha_acc, beta_acc)
    ull A1 = pk(sbga, sbc[0]);        // (gamma_acc, c0)
    ull A2 = pk(sbc[1], sbc[2]);      // (c1, c2)
    ull A3 = pk(sbc[3], sbc[4]);      // (c3, c4)

    #pragma unroll 2
    for (int jj = 0; jj < HID / 2; jj++) {
        float2 b0 = sB1[2 * jj], b1 = sB1[2 * jj + 1];
        ull a0 = pk(b0.x, b0.y);
        ull a1 = pk(b1.x, b1.y);
        #pragma unroll
        for (int i = 0; i < HID; i++) {
            float4 w = sW1[i * (HID / 2) + jj];
            ffma2(a0, u2[i], pk(w.x, w.y));
            ffma2(a1, u2[i], pk(w.z, w.w));
        }
        float x, y;
        upk(x, y, a0); float v0 = tanh_apx(x) * tanh_apx(y);
        upk(x, y, a1); float v1 = tanh_apx(x) * tanh_apx(y);

        {
            int j = 2 * jj;
            ull vv = pk(v0, v0);
            float2 p0 = sH0[j], p1 = sH1[j], p2 = sH2[j], p3 = sH3[j];
            ffma2(A0, vv, pk(p0.x, p0.y));
            ffma2(A1, vv, pk(p1.x, p1.y));
            ffma2(A2, vv, pk(p2.x, p2.y));
            ffma2(A3, vv, pk(p3.x, p3.y));
        }
        {
            int j = 2 * jj + 1;
            ull vv = pk(v1, v1);
            float2 p0 = sH0[j], p1 = sH1[j], p2 = sH2[j], p3 = sH3[j];
            ffma2(A0, vv, pk(p0.x, p0.y));
            ffma2(A1, vv, pk(p1.x, p1.y));
            ffma2(A2, vv, pk(p2.x, p2.y));
            ffma2(A3, vv, pk(p3.x, p3.y));
        }
    }

    float sa, sb, sg, c0, c1, c2, c3, c4;
    upk(sa, sb, A0);
    upk(sg, c0, A1);
    upk(c1, c2, A2);
    upk(c3, c4, A3);

    const float alpha = __expf(sa);
    const float beta  = __expf(sb);
    const float gamma = __expf(sg);

    const float zarg = fmaf(alpha, fabsf(df0), fmaf(beta, df1, gamma * fabsf(df2)));
    const float z = 1.0f - __expf(-zarg);

    float c[SD] = { c0, c1, c2, c3, c4 };
    float sigma = 0.0f;
    #pragma unroll
    for (int k = 0; k < SD; k++) {
        const float cn = tanh_acc(c[k]);
        const float hn = fmaf(z, cn - h[k], h[k]);
        out[(size_t)t * SD + k] = hn;
        sigma = fmaf(hn, sWout[k], sigma);
    }
    out[(size_t)NTOK * SD + t] = sigma;
}

extern "C" void kernel_launch(void* const* d_in, const int* in_sizes, int n_in,
                              void* d_out, int out_size) {
    const float* h_prev  = (const float*)d_in[0];
    const float* delta_x = (const float*)d_in[1];
    const float* Wa0     = (const float*)d_in[2];
    const float* ba0     = (const float*)d_in[3];
    const float* Wb0     = (const float*)d_in[4];
    const float* bb0     = (const float*)d_in[5];
    const float* Wa1     = (const float*)d_in[6];
    const float* ba1     = (const float*)d_in[7];
    const float* Wb1     = (const float*)d_in[8];
    const float* bb1     = (const float*)d_in[9];
    const float* W_alpha = (const float*)d_in[10];
    const float* b_alpha = (const float*)d_in[11];
    const float* W_beta  = (const float*)d_in[12];
    const float* b_beta  = (const float*)d_in[13];
    const float* W_gamma = (const float*)d_in[14];
    const float* b_gamma = (const float*)d_in[15];
    const float* W_c     = (const float*)d_in[16];
    const float* b_c     = (const float*)d_in[17];
    const float* W_out   = (const float*)d_in[18];
    float* out = (float*)d_out;

    cumsum_kernel<<<BATCH, 1024>>>(delta_x);
    msc_main<<<NTOK / TPB, TPB>>>(h_prev, delta_x,
                                  Wa0, ba0, Wb0, bb0,
                                  Wa1, ba1, Wb1, bb1,
                                  W_alpha, b_alpha, W_beta, b_beta,
                                  W_gamma, b_gamma, W_c, b_c, W_out,
                                  out);
}

// round 3
// speedup vs baseline: 2.0660x; 2.0660x over previous
#include <cuda_runtime.h>
#include <math.h>

#define BATCH 128
#define SEQ   4096
#define SD    5
#define HID   32
#define DIN   9
#define NTOK  (BATCH*SEQ)
#define TPB   128
#define TOKS_PER_BLOCK (TPB*4)   // 512

__device__ float g_temp[NTOK];

typedef unsigned long long ull;

__device__ __forceinline__ ull pk(float lo, float hi) {
    ull r; asm("mov.b64 %0, {%1, %2};" : "=l"(r) : "f"(lo), "f"(hi)); return r;
}
__device__ __forceinline__ void upk(float& lo, float& hi, ull v) {
    asm("mov.b64 {%0, %1}, %2;" : "=f"(lo), "=f"(hi) : "l"(v));
}
__device__ __forceinline__ void ffma2(ull& d, ull a, ull b) {
    asm("fma.rn.f32x2 %0, %1, %2, %0;" : "+l"(d) : "l"(a), "l"(b));
}
__device__ __forceinline__ ull dup(float x) { return pk(x, x); }

__device__ __forceinline__ float tanh_apx(float x) {
    float y; asm("tanh.approx.f32 %0, %1;" : "=f"(y) : "f"(x)); return y;
}
__device__ __forceinline__ float tanh_acc(float x) {
    float ax = fabsf(x);
    float e  = __expf(-2.0f * ax);
    float r  = __fdividef(1.0f - e, 1.0f + e);
    return copysignf(r, x);
}
// pack (lo,hi) f32 -> bf16x2 (lo in low half)
__device__ __forceinline__ unsigned int pk_bf2(float lo, float hi) {
    unsigned int r;
    asm("cvt.rn.bf16x2.f32 %0, %1, %2;" : "=r"(r) : "f"(hi), "f"(lo));
    return r;
}
// expand bf16x2 -> f32x2 pair
__device__ __forceinline__ ull upk_bf2(unsigned int p) {
    unsigned int lo = p << 16;
    unsigned int hi = p & 0xFFFF0000u;
    return pk(__uint_as_float(lo), __uint_as_float(hi));
}

// -------------------------------------------------------------------------
// Kernel 1: per-batch-row inclusive cumsum of delta_x[..., 2] + init temp
// -------------------------------------------------------------------------
__global__ __launch_bounds__(1024) void cumsum_kernel(const float* __restrict__ dx) {
    __shared__ float wsum[32];
    const int b    = blockIdx.x;
    const int tid  = threadIdx.x;
    const int lane = tid & 31;
    const int wid  = tid >> 5;
    const float* row = dx + (size_t)b * SEQ * 6;

    const int s0 = tid * 4;
    float v0 = row[(s0 + 0) * 6 + 2];
    float v1 = row[(s0 + 1) * 6 + 2];
    float v2 = row[(s0 + 2) * 6 + 2];
    float v3 = row[(s0 + 3) * 6 + 2];
    float p0 = v0, p1 = p0 + v1, p2 = p1 + v2, p3 = p2 + v3;
    float tot = p3;

    // warp inclusive scan of per-thread totals
    float s = tot;
    #pragma unroll
    for (int off = 1; off < 32; off <<= 1) {
        float n = __shfl_up_sync(0xffffffffu, s, off);
        if (lane >= off) s += n;
    }
    if (lane == 31) wsum[wid] = s;
    __syncthreads();
    if (wid == 0) {
        float w = wsum[lane];
        #pragma unroll
        for (int off = 1; off < 32; off <<= 1) {
            float n = __shfl_up_sync(0xffffffffu, w, off);
            if (lane >= off) w += n;
        }
        wsum[lane] = w;
    }
    __syncthreads();

    float base = row[5] + (s - tot) + ((wid > 0) ? wsum[wid - 1] : 0.0f);
    float* outp = g_temp + (size_t)b * SEQ + s0;
    outp[0] = base + p0; outp[1] = base + p1;
    outp[2] = base + p2; outp[3] = base + p3;
}

// -------------------------------------------------------------------------
// Kernel 2: 4 tokens/thread (two f32x2 pairs); weights amortized 4x.
// -------------------------------------------------------------------------
__global__ __launch_bounds__(TPB, 2) void msc_main(
    const float* __restrict__ h_prev,  const float* __restrict__ delta_x,
    const float* __restrict__ Wa0,     const float* __restrict__ ba0,
    const float* __restrict__ Wb0,     const float* __restrict__ bb0,
    const float* __restrict__ Wa1,     const float* __restrict__ ba1,
    const float* __restrict__ Wb1,     const float* __restrict__ bb1,
    const float* __restrict__ W_alpha, const float* __restrict__ b_alpha,
    const float* __restrict__ W_beta,  const float* __restrict__ b_beta,
    const float* __restrict__ W_gamma, const float* __restrict__ b_gamma,
    const float* __restrict__ W_c,     const float* __restrict__ b_c,
    const float* __restrict__ W_out,
    float* __restrict__ out)
{
    __shared__ ull  sW0[DIN * HID];          // (Wa0, Wb0) pairs
    __shared__ ull  sW1[HID * HID];          // (Wa1, Wb1) pairs
    __shared__ ull  sB0[HID], sB0g[HID];     // dup'd biases (ba,ba), (bb,bb)
    __shared__ ull  sB1[HID], sB1g[HID];
    __shared__ ull  sH[HID][4];              // head weight pairs per j
    __shared__ ull  sAinit[4];               // head accumulator inits
    __shared__ float sWout[SD];
    __shared__ uint2 u_s[HID][TPB];          // bf16x2 activations, 32 KB

    const int tid = threadIdx.x;

    for (int idx = tid; idx < HID * HID; idx += TPB)
        sW1[idx] = pk(Wa1[idx], Wb1[idx]);
    for (int idx = tid; idx < DIN * HID; idx += TPB)
        sW0[idx] = pk(Wa0[idx], Wb0[idx]);
    if (tid < HID) {
        sB0[tid]  = dup(ba0[tid]);  sB0g[tid] = dup(bb0[tid]);
        sB1[tid]  = dup(ba1[tid]);  sB1g[tid] = dup(bb1[tid]);
        sH[tid][0] = pk(W_alpha[tid],       W_beta[tid]);
        sH[tid][1] = pk(W_gamma[tid],       W_c[tid * SD + 0]);
        sH[tid][2] = pk(W_c[tid * SD + 1],  W_c[tid * SD + 2]);
        sH[tid][3] = pk(W_c[tid * SD + 3],  W_c[tid * SD + 4]);
    }
    if (tid == 0) {
        sAinit[0] = pk(b_alpha[0], b_beta[0]);
        sAinit[1] = pk(b_gamma[0], b_c[0]);
        sAinit[2] = pk(b_c[1],     b_c[2]);
        sAinit[3] = pk(b_c[3],     b_c[4]);
    }
    if (tid < SD) sWout[tid] = W_out[tid];
    __syncthreads();

    const int t0 = blockIdx.x * TOKS_PER_BLOCK + tid;   // tokens t0 + k*TPB

    // ---- load per-token inputs, build packed layer-0 input vectors ----
    ull l01[DIN], l23[DIN];
    {
        float lv[4][DIN];
        #pragma unroll
        for (int k = 0; k < 4; k++) {
            const int t = t0 + k * TPB;
            const float* hp = h_prev  + (size_t)t * SD;
            const float* dx = delta_x + (size_t)t * 6;
            #pragma unroll
            for (int d = 0; d < SD; d++) lv[k][d] = hp[d];
            float d0 = dx[0], d1 = dx[1], d2 = dx[2];
            float nrm = sqrtf(fmaf(d0, d0, fmaf(d1, d1, d2 * d2)));
            nrm = fmaxf(nrm, 1e-7f);
            float inv = __fdividef(1.0f, nrm);
            lv[k][5] = g_temp[t];
            lv[k][6] = d0 * inv; lv[k][7] = d1 * inv; lv[k][8] = d2 * inv;
        }
        #pragma unroll
        for (int d = 0; d < DIN; d++) {
            l01[d] = pk(lv[0][d], lv[1][d]);
            l23[d] = pk(lv[2][d], lv[3][d]);
        }
    }

    // ---------------- layer 0: 9 -> 32 gated, results to u_s (bf16x2) ----
    #pragma unroll 1
    for (int j = 0; j < HID; j++) {
        ull a01 = sB0[j],  a23 = a01;
        ull b01 = sB0g[j], b23 = b01;
        #pragma unroll
        for (int i = 0; i < DIN; i++) {
            ull w = sW0[i * HID + j];
            float wa, wb; upk(wa, wb, w);
            ull wad = dup(wa), wbd = dup(wb);
            ffma2(a01, l01[i], wad);
            ffma2(a23, l23[i], wad);
            ffma2(b01, l01[i], wbd);
            ffma2(b23, l23[i], wbd);
        }
        float x0, x1, x2, x3, y0, y1, y2, y3;
        upk(x0, x1, a01); upk(x2, x3, a23);
        upk(y0, y1, b01); upk(y2, y3, b23);
        float u0 = tanh_apx(x0) * tanh_apx(y0);
        float u1 = tanh_apx(x1) * tanh_apx(y1);
        float u2 = tanh_apx(x2) * tanh_apx(y2);
        float u3 = tanh_apx(x3) * tanh_apx(y3);
        u_s[j][tid] = make_uint2(pk_bf2(u0, u1), pk_bf2(u2, u3));
    }

    // no __syncthreads needed: each thread reads only its own u_s column

    // ---- pull activations back into registers as f32x2 token pairs ----
    ull u01[HID], u23[HID];
    #pragma unroll
    for (int i = 0; i < HID; i++) {
        uint2 p = u_s[i][tid];
        u01[i] = upk_bf2(p.x);
        u23[i] = upk_bf2(p.y);
    }

    // ---------------- layer 1 (32->32 gated) fused with heads -----------
    ull A0_0 = sAinit[0], A0_1 = A0_0, A0_2 = A0_0, A0_3 = A0_0;
    ull A1_0 = sAinit[1], A1_1 = A1_0, A1_2 = A1_0, A1_3 = A1_0;
    ull A2_0 = sAinit[2], A2_1 = A2_0, A2_2 = A2_0, A2_3 = A2_0;
    ull A3_0 = sAinit[3], A3_1 = A3_0, A3_2 = A3_0, A3_3 = A3_0;

    #pragma unroll 1
    for (int j = 0; j < HID; j++) {
        ull a01 = sB1[j],  a23 = a01;
        ull b01 = sB1g[j], b23 = b01;
        #pragma unroll
        for (int i = 0; i < HID; i++) {
            ull w = sW1[i * HID + j];
            float wa, wb; upk(wa, wb, w);
            ull wad = dup(wa), wbd = dup(wb);
            ffma2(a01, u01[i], wad);
            ffma2(a23, u23[i], wad);
            ffma2(b01, u01[i], wbd);
            ffma2(b23, u23[i], wbd);
        }
        float x0, x1, x2, x3, y0, y1, y2, y3;
        upk(x0, x1, a01); upk(x2, x3, a23);
        upk(y0, y1, b01); upk(y2, y3, b23);
        float v0 = tanh_apx(x0) * tanh_apx(y0);
        float v1 = tanh_apx(x1) * tanh_apx(y1);
        float v2 = tanh_apx(x2) * tanh_apx(y2);
        float v3 = tanh_apx(x3) * tanh_apx(y3);

        ull hw0 = sH[j][0], hw1 = sH[j][1], hw2 = sH[j][2], hw3 = sH[j][3];
        ull vd;
        vd = dup(v0); ffma2(A0_0, vd, hw0); ffma2(A1_0, vd, hw1);
                      ffma2(A2_0, vd, hw2); ffma2(A3_0, vd, hw3);
        vd = dup(v1); ffma2(A0_1, vd, hw0); ffma2(A1_1, vd, hw1);
                      ffma2(A2_1, vd, hw2); ffma2(A3_1, vd, hw3);
        vd = dup(v2); ffma2(A0_2, vd, hw0); ffma2(A1_2, vd, hw1);
                      ffma2(A2_2, vd, hw2); ffma2(A3_2, vd, hw3);
        vd = dup(v3); ffma2(A0_3, vd, hw0); ffma2(A1_3, vd, hw1);
                      ffma2(A2_3, vd, hw2); ffma2(A3_3, vd, hw3);
    }

    // ---------------- tail: per-token heads, gate, outputs ---------------
    ull A0k[4] = { A0_0, A0_1, A0_2, A0_3 };
    ull A1k[4] = { A1_0, A1_1, A1_2, A1_3 };
    ull A2k[4] = { A2_0, A2_1, A2_2, A2_3 };
    ull A3k[4] = { A3_0, A3_1, A3_2, A3_3 };

    #pragma unroll
    for (int k = 0; k < 4; k++) {
        const int t = t0 + k * TPB;
        const float* dx = delta_x + (size_t)t * 6;
        const float* hp = h_prev  + (size_t)t * SD;

        float sa, sb, sg, c0, c1, c2, c3, c4;
        upk(sa, sb, A0k[k]);
        upk(sg, c0, A1k[k]);
        upk(c1, c2, A2k[k]);
        upk(c3, c4, A3k[k]);

        const float alpha = __expf(sa);
        const float beta  = __expf(sb);
        const float gamma = __expf(sg);

        const float d0 = dx[0], d1 = dx[1], d2 = dx[2];
        const float zarg = fmaf(alpha, fabsf(d0), fmaf(beta, d1, gamma * fabsf(d2)));
        const float z = 1.0f - __expf(-zarg);

        float c[SD] = { c0, c1, c2, c3, c4 };
        float sigma = 0.0f;
        #pragma unroll
        for (int d = 0; d < SD; d++) {
            const float hv = hp[d];
            const float cn = tanh_acc(c[d]);
            const float hn = fmaf(z, cn - hv, hv);
            out[(size_t)t * SD + d] = hn;
            sigma = fmaf(hn, sWout[d], sigma);
        }
        out[(size_t)NTOK * SD + t] = sigma;
    }
}

extern "C" void kernel_launch(void* const* d_in, const int* in_sizes, int n_in,
                              void* d_out, int out_size) {
    const float* h_prev  = (const float*)d_in[0];
    const float* delta_x = (const float*)d_in[1];
    const float* Wa0     = (const float*)d_in[2];
    const float* ba0     = (const float*)d_in[3];
    const float* Wb0     = (const float*)d_in[4];
    const float* bb0     = (const float*)d_in[5];
    const float* Wa1     = (const float*)d_in[6];
    const float* ba1     = (const float*)d_in[7];
    const float* Wb1     = (const float*)d_in[8];
    const float* bb1     = (const float*)d_in[9];
    const float* W_alpha = (const float*)d_in[10];
    const float* b_alpha = (const float*)d_in[11];
    const float* W_beta  = (const float*)d_in[12];
    const float* b_beta  = (const float*)d_in[13];
    const float* W_gamma = (const float*)d_in[14];
    const float* b_gamma = (const float*)d_in[15];
    const float* W_c     = (const float*)d_in[16];
    const float* b_c     = (const float*)d_in[17];
    const float* W_out   = (const float*)d_in[18];
    float* out = (float*)d_out;

    cumsum_kernel<<<BATCH, 1024>>>(delta_x);
    msc_main<<<NTOK / TOKS_PER_BLOCK, TPB>>>(h_prev, delta_x,
                                             Wa0, ba0, Wb0, bb0,
                                             Wa1, ba1, Wb1, bb1,
                                             W_alpha, b_alpha, W_beta, b_beta,
                                             W_gamma, b_gamma, W_c, b_c, W_out,
                                             out);
}